// round 7
// baseline (speedup 1.0000x reference)
#include <cuda_runtime.h>
#include <math.h>

// Problem constants
#define IMG_H 512
#define IMG_W 512
#define BATCH 16
#define CH    3
#define TILE  32
#define HALO  3
#define RAW   38          // TILE + 2*HALO
#define RAWP  39          // raw shared pitch (odd -> conflict-free column access)
#define HP    33          // h-sum shared pitch
#define NTHREADS 256
#define NBLOCKS  (BATCH * (IMG_H/TILE) * (IMG_W/TILE))   // 4096
#define INV_N    (1.0f / 147.0f)                         // C*K*K = 147
#define EPS      1e-8f
#define TOTAL_PIX ((float)(BATCH) * IMG_H * IMG_W)       // 4194304

__device__ float g_partials[NBLOCKS];

// Compute per-pixel local std for a 32x32 tile of one image.
// stdv[0..3] are the 4 consecutive rows owned by this thread (col = tid&31,
// rows r0..r0+3 with r0 = (tid>>5)*4).
__device__ __forceinline__ void process_image(
    const float* __restrict__ x, int b, int baseH, int baseW,
    float* __restrict__ sy, float* __restrict__ sy2,
    float* __restrict__ hy, float* __restrict__ hy2,
    float stdv[4], int tid)
{
    const float* p0 = x + (size_t)b * CH * IMG_H * IMG_W;

    // ---- Phase A: load halo tile, fold channels: y = sum_c x, y2 = sum_c x^2
    for (int i = tid; i < RAW * RAW; i += NTHREADS) {
        int r = i / RAW, c = i - r * RAW;
        int gh = baseH + r - HALO, gw = baseW + c - HALO;
        float y = 0.f, y2 = 0.f;
        if ((unsigned)gh < (unsigned)IMG_H && (unsigned)gw < (unsigned)IMG_W) {
            int off = gh * IMG_W + gw;
            float v0 = __ldg(p0 + off);
            float v1 = __ldg(p0 + off + IMG_H * IMG_W);
            float v2 = __ldg(p0 + off + 2 * IMG_H * IMG_W);
            y  = v0 + v1 + v2;
            y2 = v0 * v0 + v1 * v1 + v2 * v2;
        }
        sy [r * RAWP + c] = y;
        sy2[r * RAWP + c] = y2;
    }
    __syncthreads();

    // ---- Phase B: horizontal 7-tap running sums (one row per thread, 76 rows of work)
    if (tid < 2 * RAW) {
        int which = (tid >= RAW);
        int r = which ? (tid - RAW) : tid;
        const float* row = (which ? sy2 : sy) + r * RAWP;
        float* drow      = (which ? hy2 : hy) + r * HP;
        float run = row[0] + row[1] + row[2] + row[3] + row[4] + row[5] + row[6];
        drow[0] = run;
        #pragma unroll
        for (int c = 1; c < TILE; c++) {
            run += row[c + 6] - row[c - 1];
            drow[c] = run;
        }
    }
    __syncthreads();

    // ---- Phase C: vertical 7-tap running sums + std, 4 consecutive rows/thread
    int c  = tid & 31;
    int r0 = (tid >> 5) * 4;
    float s = 0.f, s2 = 0.f;
    #pragma unroll
    for (int k = 0; k < 7; k++) {
        s  += hy [(r0 + k) * HP + c];
        s2 += hy2[(r0 + k) * HP + c];
    }
    #pragma unroll
    for (int j = 0; j < 4; j++) {
        float mu  = s * INV_N;
        float var = s2 * INV_N - mu * mu;
        stdv[j] = sqrtf(var + EPS);
        if (j < 3) {
            s  += hy [(r0 + j + 7) * HP + c] - hy [(r0 + j) * HP + c];
            s2 += hy2[(r0 + j + 7) * HP + c] - hy2[(r0 + j) * HP + c];
        }
    }
    __syncthreads();   // protect shared reuse by the next image
}

__global__ __launch_bounds__(NTHREADS)
void distloss_tile_kernel(const float* __restrict__ pred,
                          const float* __restrict__ tgt)
{
    __shared__ float sy [RAW * RAWP];
    __shared__ float sy2[RAW * RAWP];
    __shared__ float hy [RAW * HP];
    __shared__ float hy2[RAW * HP];
    __shared__ float red[8];

    int tid   = threadIdx.x;
    int b     = blockIdx.z;
    int baseH = blockIdx.y * TILE;
    int baseW = blockIdx.x * TILE;

    float sp[4], st[4];
    process_image(pred, b, baseH, baseW, sy, sy2, hy, hy2, sp, tid);
    process_image(tgt,  b, baseH, baseW, sy, sy2, hy, hy2, st, tid);

    // Smooth-L1 over this thread's 4 pixels
    float local = 0.f;
    #pragma unroll
    for (int j = 0; j < 4; j++) {
        float d  = sp[j] - st[j];
        float ad = fabsf(d);
        local += (ad < 1.f) ? 0.5f * d * d : (ad - 0.5f);
    }

    // Block reduction: warp shuffles, then 8 warp leaders
    #pragma unroll
    for (int off = 16; off > 0; off >>= 1)
        local += __shfl_down_sync(0xFFFFFFFFu, local, off);
    if ((tid & 31) == 0) red[tid >> 5] = local;
    __syncthreads();
    if (tid == 0) {
        float bs = 0.f;
        #pragma unroll
        for (int w = 0; w < 8; w++) bs += red[w];
        int bidx = (blockIdx.z * gridDim.y + blockIdx.y) * gridDim.x + blockIdx.x;
        g_partials[bidx] = bs;
    }
}

__global__ __launch_bounds__(NTHREADS)
void distloss_finalize_kernel(float* __restrict__ out)
{
    __shared__ float sh[NTHREADS];
    int tid = threadIdx.x;
    float s = 0.f;
    #pragma unroll
    for (int i = tid; i < NBLOCKS; i += NTHREADS)
        s += g_partials[i];
    sh[tid] = s;
    __syncthreads();
    #pragma unroll
    for (int step = NTHREADS / 2; step > 0; step >>= 1) {
        if (tid < step) sh[tid] += sh[tid + step];
        __syncthreads();
    }
    if (tid == 0) out[0] = sh[0] * (1.0f / TOTAL_PIX);
}

extern "C" void kernel_launch(void* const* d_in, const int* in_sizes, int n_in,
                              void* d_out, int out_size)
{
    const float* pred = (const float*)d_in[0];  // pred_moire
    const float* tgt  = (const float*)d_in[1];  // moire
    dim3 grid(IMG_W / TILE, IMG_H / TILE, BATCH);   // (16,16,16) = 4096 blocks
    distloss_tile_kernel<<<grid, NTHREADS>>>(pred, tgt);
    distloss_finalize_kernel<<<1, NTHREADS>>>((float*)d_out);
}

// round 11
// speedup vs baseline: 1.1852x; 1.1852x over previous
#include <cuda_runtime.h>
#include <math.h>

#define IMG_H 512
#define IMG_W 512
#define BATCH 16
#define TILE  32
#define HALO  3
#define RAW   38                 // TILE + 2*HALO
#define RAWP  39                 // odd pitch -> conflict-free strided row access
#define NTHREADS 256
#define GX (IMG_W / TILE)        // 16
#define GY (IMG_H / TILE)        // 16
#define NBLOCKS (BATCH * GX * GY)  // 4096
#define CHSTRIDE (IMG_H * IMG_W)
#define INV_N    (1.0f / 147.0f) // C*K*K
#define EPS      1e-8f
#define INV_TOTAL (1.0f / 4194304.0f)  // 1/(B*H*W)

__device__ float        g_partials[NBLOCKS];
__device__ unsigned int g_count = 0;

__global__ __launch_bounds__(NTHREADS)
void distloss_kernel(const float* __restrict__ pred,
                     const float* __restrict__ tgt,
                     float* __restrict__ out)
{
    // raw[0]=pred y, raw[1]=pred y2, raw[2]=tgt y, raw[3]=tgt y2
    // After Phase B, cols 0..31 of each row hold the horizontal 7-tap sums (in-place).
    __shared__ float raw[4][RAW * RAWP];
    __shared__ float red[8];
    __shared__ bool  isLast;

    const int tid   = threadIdx.x;
    const int b     = blockIdx.z;
    const int baseH = blockIdx.y * TILE;
    const int baseW = blockIdx.x * TILE;

    const float* pB = pred + (size_t)b * 3 * CHSTRIDE;
    const float* tB = tgt  + (size_t)b * 3 * CHSTRIDE;

    const bool interior =
        (baseH >= HALO) && (baseH + TILE + HALO <= IMG_H) &&
        (baseW >= HALO) && (baseW + TILE + HALO <= IMG_W);

    // ---- Phase A: load halo tiles for BOTH images, fold channels (y, y^2)
    if (interior) {
        const float* p0 = pB + (baseH - HALO) * IMG_W + (baseW - HALO);
        const float* t0 = tB + (baseH - HALO) * IMG_W + (baseW - HALO);
        #pragma unroll
        for (int k = 0; k < 6; k++) {
            int i = tid + k * NTHREADS;
            if (i < RAW * RAW) {
                int r = i / RAW, c = i - r * RAW;
                int off = r * IMG_W + c;
                float a0 = __ldg(p0 + off);
                float a1 = __ldg(p0 + off + CHSTRIDE);
                float a2 = __ldg(p0 + off + 2 * CHSTRIDE);
                float b0 = __ldg(t0 + off);
                float b1 = __ldg(t0 + off + CHSTRIDE);
                float b2 = __ldg(t0 + off + 2 * CHSTRIDE);
                int s = r * RAWP + c;
                raw[0][s] = a0 + a1 + a2;
                raw[1][s] = a0 * a0 + a1 * a1 + a2 * a2;
                raw[2][s] = b0 + b1 + b2;
                raw[3][s] = b0 * b0 + b1 * b1 + b2 * b2;
            }
        }
    } else {
        #pragma unroll
        for (int k = 0; k < 6; k++) {
            int i = tid + k * NTHREADS;
            if (i < RAW * RAW) {
                int r = i / RAW, c = i - r * RAW;
                int gh = baseH + r - HALO, gw = baseW + c - HALO;
                float a0 = 0.f, a1 = 0.f, a2 = 0.f;
                float b0 = 0.f, b1 = 0.f, b2 = 0.f;
                if ((unsigned)gh < (unsigned)IMG_H && (unsigned)gw < (unsigned)IMG_W) {
                    int off = gh * IMG_W + gw;
                    a0 = __ldg(pB + off);
                    a1 = __ldg(pB + off + CHSTRIDE);
                    a2 = __ldg(pB + off + 2 * CHSTRIDE);
                    b0 = __ldg(tB + off);
                    b1 = __ldg(tB + off + CHSTRIDE);
                    b2 = __ldg(tB + off + 2 * CHSTRIDE);
                }
                int s = r * RAWP + c;
                raw[0][s] = a0 + a1 + a2;
                raw[1][s] = a0 * a0 + a1 * a1 + a2 * a2;
                raw[2][s] = b0 + b1 + b2;
                raw[3][s] = b0 * b0 + b1 * b1 + b2 * b2;
            }
        }
    }
    __syncthreads();

    // ---- Phase B: horizontal 7-tap running sums, written IN-PLACE (1-step delay:
    // raw[c-1] is dead once subtracted from the running sum).
    if (tid < 4 * RAW) {
        int which = tid / RAW;
        int r     = tid - which * RAW;
        float* row = &raw[which][r * RAWP];
        float run = row[0] + row[1] + row[2] + row[3] + row[4] + row[5] + row[6];
        float hprev = run;
        #pragma unroll
        for (int c = 1; c < TILE; c++) {
            float add = row[c + 6];
            float sub = row[c - 1];
            run += add - sub;
            row[c - 1] = hprev;
            hprev = run;
        }
        row[TILE - 1] = hprev;
    }
    __syncthreads();

    // ---- Phase C: vertical 7-tap running sums + std + smooth-L1
    const int c  = tid & 31;
    const int r0 = (tid >> 5) * 4;

    float sp[4];
    {
        float s = 0.f, s2 = 0.f;
        #pragma unroll
        for (int k = 0; k < 7; k++) {
            s  += raw[0][(r0 + k) * RAWP + c];
            s2 += raw[1][(r0 + k) * RAWP + c];
        }
        #pragma unroll
        for (int j = 0; j < 4; j++) {
            float mu  = s * INV_N;
            float var = s2 * INV_N - mu * mu;
            sp[j] = sqrtf(var + EPS);
            if (j < 3) {
                s  += raw[0][(r0 + j + 7) * RAWP + c] - raw[0][(r0 + j) * RAWP + c];
                s2 += raw[1][(r0 + j + 7) * RAWP + c] - raw[1][(r0 + j) * RAWP + c];
            }
        }
    }
    float local = 0.f;
    {
        float s = 0.f, s2 = 0.f;
        #pragma unroll
        for (int k = 0; k < 7; k++) {
            s  += raw[2][(r0 + k) * RAWP + c];
            s2 += raw[3][(r0 + k) * RAWP + c];
        }
        #pragma unroll
        for (int j = 0; j < 4; j++) {
            float mu  = s * INV_N;
            float var = s2 * INV_N - mu * mu;
            float st  = sqrtf(var + EPS);
            float d   = sp[j] - st;
            float ad  = fabsf(d);
            local += (ad < 1.f) ? 0.5f * d * d : (ad - 0.5f);
            if (j < 3) {
                s  += raw[2][(r0 + j + 7) * RAWP + c] - raw[2][(r0 + j) * RAWP + c];
                s2 += raw[3][(r0 + j + 7) * RAWP + c] - raw[3][(r0 + j) * RAWP + c];
            }
        }
    }

    // ---- Block reduction
    #pragma unroll
    for (int off = 16; off > 0; off >>= 1)
        local += __shfl_down_sync(0xFFFFFFFFu, local, off);
    if ((tid & 31) == 0) red[tid >> 5] = local;
    __syncthreads();

    if (tid == 0) {
        float bs = 0.f;
        #pragma unroll
        for (int w = 0; w < 8; w++) bs += red[w];
        int bidx = (blockIdx.z * GY + blockIdx.y) * GX + blockIdx.x;
        g_partials[bidx] = bs;
        __threadfence();
        unsigned old = atomicAdd(&g_count, 1u);
        isLast = (old == NBLOCKS - 1);
    }
    __syncthreads();

    // ---- Last block: deterministic final sum (fixed order), reset counter
    if (isLast) {
        float s = 0.f;
        for (int i = tid; i < NBLOCKS; i += NTHREADS)
            s += __ldcg(&g_partials[i]);
        #pragma unroll
        for (int off = 16; off > 0; off >>= 1)
            s += __shfl_down_sync(0xFFFFFFFFu, s, off);
        if ((tid & 31) == 0) red[tid >> 5] = s;
        __syncthreads();
        if (tid == 0) {
            float tot = 0.f;
            #pragma unroll
            for (int w = 0; w < 8; w++) tot += red[w];
            out[0] = tot * INV_TOTAL;
            g_count = 0;  // ready for next graph replay
        }
    }
}

extern "C" void kernel_launch(void* const* d_in, const int* in_sizes, int n_in,
                              void* d_out, int out_size)
{
    const float* pred = (const float*)d_in[0];  // pred_moire
    const float* tgt  = (const float*)d_in[1];  // moire
    dim3 grid(GX, GY, BATCH);                   // 4096 blocks
    distloss_kernel<<<grid, NTHREADS>>>(pred, tgt, (float*)d_out);
}